// round 12
// baseline (speedup 1.0000x reference)
#include <cuda_runtime.h>
#include <cuda_fp16.h>
#include <cstdint>
#include <math.h>

#define BATCH 8192
#define DIM   512
#define HID   2048
#define NSTEPS 10

// ---------------- tile config ----------------
#define BM 128
#define BN 128
#define BK 64                        // K elems per stage (64 fp16 = 128B rows)
#define STAGE 32768                  // A 16K + W 16K
#define NSTAGE 3
#define SMEM_DYN (NSTAGE * STAGE + 1024)

// ---------------- scratch (__device__ globals; allocation-free rule) ----------------
__device__ __align__(16) __half g_hid16[(size_t)BATCH * HID];   // tanh activations
__device__ __align__(16) __half g_y16  [(size_t)BATCH * DIM];   // y (fp16 view)
__device__ __align__(16) __half g_yt16 [(size_t)BATCH * DIM];   // ytmp (fp16 view)
__device__ __align__(16) float  g_k1   [(size_t)BATCH * DIM];
__device__ __align__(16) float  g_yf   [(size_t)BATCH * DIM];   // y state fp32
__device__ __align__(16) __half g_w1t  [(size_t)DIM * HID];     // W1^T [HID,DIM] K-major
__device__ __align__(16) __half g_w2t  [(size_t)HID * DIM];     // W2^T [DIM,HID] K-major

// ---------------- helpers (baseline PTX only; no sm_*a features) ----------------
__device__ __forceinline__ uint32_t smem_u32(const void* p) {
    uint32_t a;
    asm("{ .reg .u64 t; cvta.to.shared.u64 t, %1; cvt.u32.u64 %0, t; }" : "=r"(a) : "l"(p));
    return a;
}
#define SWZ(o) ((uint32_t)(o) ^ ((((uint32_t)(o)) >> 3) & 0x70u))

__device__ __forceinline__ void cp16(uint32_t s, const void* g) {
    asm volatile("cp.async.cg.shared.global [%0], [%1], 16;" :: "r"(s), "l"(g));
}
#define CP_COMMIT() asm volatile("cp.async.commit_group;" ::: "memory")
#define CP_WAIT(n)  asm volatile("cp.async.wait_group %0;" :: "n"(n) : "memory")

__device__ __forceinline__ void ldsm4(uint32_t& r0, uint32_t& r1, uint32_t& r2, uint32_t& r3,
                                      uint32_t addr) {
    asm volatile("ldmatrix.sync.aligned.m8n8.x4.shared.b16 {%0,%1,%2,%3}, [%4];"
                 : "=r"(r0), "=r"(r1), "=r"(r2), "=r"(r3) : "r"(addr));
}
__device__ __forceinline__ void mma16816h(float* c, const uint32_t* a, const uint32_t* b) {
    asm volatile("mma.sync.aligned.m16n8k16.row.col.f32.f16.f16.f32 "
                 "{%0,%1,%2,%3}, {%4,%5,%6,%7}, {%8,%9}, {%0,%1,%2,%3};"
                 : "+f"(c[0]), "+f"(c[1]), "+f"(c[2]), "+f"(c[3])
                 : "r"(a[0]), "r"(a[1]), "r"(a[2]), "r"(a[3]), "r"(b[0]), "r"(b[1]));
}

// ---------------- stage loader: 2 tiles of [128 rows x 128B], 256 threads ----------------
__device__ __forceinline__ void load_stage(
    uint32_t st,
    const __half* __restrict__ A, const __half* __restrict__ W,
    int bm, int bn, int K, int kc0, int tid)
{
#pragma unroll
    for (int i = 0; i < 4; i++) {
        const int lin = i * 256 + tid;
        const int row = lin >> 3;
        const uint32_t q16 = (uint32_t)(lin & 7) * 16u;
        const uint32_t so = SWZ((uint32_t)row * 128u + q16);
        cp16(st + so,          (const char*)A + ((size_t)(bm + row) * K + kc0) * 2 + q16);
        cp16(st + 16384u + so, (const char*)W + ((size_t)(bn + row) * K + kc0) * 2 + q16);
    }
    CP_COMMIT();
}

// ---------------- fused fp16 HMMA GEMM: C = A @ W^T + bias ----------------
//  EPI 0: v = tanh(c)                      -> oh (fp16)
//  EPI 1: outf = c (k1);  v = yin+0.1c     -> oh (fp16 ytmp)
//  EPI 2: v = yin+0.05(k1in+c); outf = v   -> oh (fp16 y_next)
template <int EPI>
__global__ void __launch_bounds__(256, 2) ode_gemm(
    const __half* __restrict__ A, const __half* __restrict__ W,
    const float* __restrict__ bias, int N, int K,
    const float* __restrict__ yin, const float* __restrict__ k1in,
    float* __restrict__ outf, __half* __restrict__ oh)
{
    extern __shared__ char dyn[];
    const uint32_t sb = (smem_u32(dyn) + 1023u) & ~1023u;

    const int tid = threadIdx.x;
    const int wid = tid >> 5, lane = tid & 31;
    const int warp_m = wid >> 2, warp_n = wid & 3;     // 2 x 4 warps, 64x32 warp tile
    const int kph = wid & 3;                           // per-warp ks phase stagger
    const int bm = blockIdx.y * BM, bn = blockIdx.x * BN;

    float acc[4][4][4];
#pragma unroll
    for (int mt = 0; mt < 4; mt++)
#pragma unroll
        for (int nt = 0; nt < 4; nt++)
#pragma unroll
            for (int r = 0; r < 4; r++) acc[mt][nt][r] = 0.f;

    const int nit = K >> 6;
    load_stage(sb,         A, W, bm, bn, K, 0,  tid);
    load_stage(sb + STAGE, A, W, bm, bn, K, BK, tid);

    // per-lane ldmatrix byte offsets (pre-swizzle)
    const uint32_t aOff = (uint32_t)(warp_m * 64 + (lane & 15)) * 128u + (uint32_t)(lane >> 4) * 16u;
    const uint32_t bOff = (uint32_t)(warp_n * 32 + (lane & 7) + ((lane >> 4) << 3)) * 128u
                        + (uint32_t)((lane >> 3) & 1) * 16u;

#pragma unroll 1
    for (int c = 0; c < nit; c++) {
        if (c + 1 < nit) CP_WAIT(1); else CP_WAIT(0);
        __syncthreads();
        // slot (c+2)%3 last held stage c-1, fully consumed before this barrier
        if (c + 2 < nit)
            load_stage(sb + (uint32_t)((c + 2) % NSTAGE) * STAGE, A, W, bm, bn, K,
                       (c + 2) * BK, tid);

        const uint32_t st = sb + (uint32_t)(c % NSTAGE) * STAGE;
        // ks-phase stagger: warp w starts at ks=(w&3) so at any instant ~1/4 of
        // warps are in their LDS/ldmatrix phase and ~3/4 are issuing MMAs —
        // de-phases smem-crossbar bursts from tensor bursts across the SM.
#pragma unroll
        for (int ksi = 0; ksi < 4; ksi++) {
            const int ks = (ksi + kph) & 3;
            uint32_t ah[4][4], bh[2][4];
#pragma unroll
            for (int mt = 0; mt < 4; mt++) {
                const uint32_t o = SWZ(aOff + (uint32_t)mt * 2048u + (uint32_t)ks * 32u);
                ldsm4(ah[mt][0], ah[mt][1], ah[mt][2], ah[mt][3], st + o);
            }
#pragma unroll
            for (int nb = 0; nb < 2; nb++) {
                const uint32_t o = SWZ(bOff + (uint32_t)nb * 2048u + (uint32_t)ks * 32u);
                ldsm4(bh[nb][0], bh[nb][1], bh[nb][2], bh[nb][3], st + 16384u + o);
            }
#pragma unroll
            for (int mt = 0; mt < 4; mt++)
#pragma unroll
                for (int nt = 0; nt < 4; nt++)
                    mma16816h(acc[mt][nt], ah[mt], &bh[nt >> 1][(nt & 1) * 2]);
        }
    }

    // ---------------- epilogue from register accumulators ----------------
    const int row0 = bm + warp_m * 64 + (lane >> 2);
    const int col0 = bn + warp_n * 32 + (lane & 3) * 2;
#pragma unroll
    for (int mt = 0; mt < 4; mt++)
#pragma unroll
        for (int nt = 0; nt < 4; nt++) {
            const int ccol = col0 + nt * 8;
            const float2 bv = *(const float2*)(bias + ccol);
#pragma unroll
            for (int h = 0; h < 2; h++) {
                const int r = row0 + mt * 16 + 8 * h;
                const size_t idx = (size_t)r * N + ccol;
                float x0 = acc[mt][nt][2 * h]     + bv.x;
                float x1 = acc[mt][nt][2 * h + 1] + bv.y;
                float v0, v1;
                if (EPI == 0) {
                    const float e0 = __expf(2.0f * x0);
                    const float e1 = __expf(2.0f * x1);
                    v0 = 1.0f - __fdividef(2.0f, e0 + 1.0f);
                    v1 = 1.0f - __fdividef(2.0f, e1 + 1.0f);
                } else if (EPI == 1) {
                    *(float2*)(outf + idx) = make_float2(x0, x1);
                    const float2 yv = *(const float2*)(yin + idx);
                    v0 = yv.x + 0.1f * x0;
                    v1 = yv.y + 0.1f * x1;
                } else {
                    const float2 yv = *(const float2*)(yin + idx);
                    const float2 kv = *(const float2*)(k1in + idx);
                    v0 = yv.x + 0.05f * (kv.x + x0);
                    v1 = yv.y + 0.05f * (kv.y + x1);
                    *(float2*)(outf + idx) = make_float2(v0, v1);
                }
                *(__half2*)(oh + idx) = __floats2half2_rn(v0, v1);
            }
        }
}

// ---------------- conversion kernels ----------------
__global__ void to_f16(const float* __restrict__ x, __half* __restrict__ o, int n)
{
    int i = blockIdx.x * blockDim.x + threadIdx.x;
    if (i < n) o[i] = __float2half(x[i]);
}

// W[K,N] row-major -> Wt[N,K] fp16 (K-major B operand)
__global__ void transpose_f16(const float* __restrict__ W, int K, int N,
                              __half* __restrict__ o)
{
    __shared__ float t[32][33];
    const int nx = blockIdx.x * 32 + threadIdx.x;
    const int ky = blockIdx.y * 32 + threadIdx.y;
#pragma unroll
    for (int i = 0; i < 32; i += 8)
        t[threadIdx.y + i][threadIdx.x] = W[(size_t)(ky + i) * N + nx];
    __syncthreads();
    const int on = blockIdx.x * 32 + threadIdx.y;
    const int ok = blockIdx.y * 32 + threadIdx.x;
#pragma unroll
    for (int i = 0; i < 32; i += 8)
        o[(size_t)(on + i) * K + ok] = __float2half(t[threadIdx.x][threadIdx.y + i]);
}

// ---------------- host ----------------
extern "C" void kernel_launch(void* const* d_in, const int* in_sizes, int n_in,
                              void* d_out, int out_size)
{
    const float* y0 = (const float*)d_in[0];
    const float* W1 = (const float*)d_in[1];
    const float* b1 = (const float*)d_in[2];
    const float* W2 = (const float*)d_in[3];
    const float* b2 = (const float*)d_in[4];
    float* yout = (float*)d_out;

    __half *hid16, *y16, *yt16, *w1t, *w2t;
    float *k1f, *yf;
    cudaGetSymbolAddress((void**)&hid16, g_hid16);
    cudaGetSymbolAddress((void**)&y16,   g_y16);
    cudaGetSymbolAddress((void**)&yt16,  g_yt16);
    cudaGetSymbolAddress((void**)&k1f,   g_k1);
    cudaGetSymbolAddress((void**)&yf,    g_yf);
    cudaGetSymbolAddress((void**)&w1t,   g_w1t);
    cudaGetSymbolAddress((void**)&w2t,   g_w2t);

    cudaFuncSetAttribute(ode_gemm<0>, cudaFuncAttributeMaxDynamicSharedMemorySize, SMEM_DYN);
    cudaFuncSetAttribute(ode_gemm<1>, cudaFuncAttributeMaxDynamicSharedMemorySize, SMEM_DYN);
    cudaFuncSetAttribute(ode_gemm<2>, cudaFuncAttributeMaxDynamicSharedMemorySize, SMEM_DYN);

    to_f16<<<(BATCH * DIM + 255) / 256, 256>>>(y0, y16, BATCH * DIM);
    transpose_f16<<<dim3(HID / 32, DIM / 32), dim3(32, 8)>>>(W1, DIM, HID, w1t);
    transpose_f16<<<dim3(DIM / 32, HID / 32), dim3(32, 8)>>>(W2, HID, DIM, w2t);

    const dim3 g1(HID / BN, BATCH / BM);   // (16, 64)
    const dim3 g2(DIM / BN, BATCH / BM);   // (4, 64)

    const float* ycur = y0;
    for (int s = 0; s < NSTEPS; s++) {
        // k1 = f(y): hidden = tanh(y@W1+b1); k1 = hidden@W2+b2; ytmp = y + dt*k1
        ode_gemm<0><<<g1, 256, SMEM_DYN>>>(y16,   w1t, b1, HID, DIM,
                                           nullptr, nullptr, nullptr, hid16);
        ode_gemm<1><<<g2, 256, SMEM_DYN>>>(hid16, w2t, b2, DIM, HID,
                                           ycur, nullptr, k1f, yt16);
        // k2 = f(ytmp); y = y + 0.5*dt*(k1+k2)
        ode_gemm<0><<<g1, 256, SMEM_DYN>>>(yt16,  w1t, b1, HID, DIM,
                                           nullptr, nullptr, nullptr, hid16);
        float* of = (s == NSTEPS - 1) ? yout : yf;
        ode_gemm<2><<<g2, 256, SMEM_DYN>>>(hid16, w2t, b2, DIM, HID,
                                           ycur, k1f, of, y16);
        ycur = yf;
    }
}